// round 13
// baseline (speedup 1.0000x reference)
#include <cuda_runtime.h>
#include <cuda_bf16.h>
#include <cstdint>

#define B 4
#define C 128
#define CM 64
#define CO 100
#define HO 128
#define WO 128

typedef unsigned long long u64;

// ---------------- packed f32x2 helpers (k1/k3 scalar paths) ----------------
__device__ __forceinline__ u64 pk(float lo, float hi) {
    u64 r; asm("mov.b64 %0, {%1,%2};" : "=l"(r) : "f"(lo), "f"(hi)); return r;
}
__device__ __forceinline__ float2 upk(u64 v) {
    float2 f; asm("mov.b64 {%0,%1}, %2;" : "=f"(f.x), "=f"(f.y) : "l"(v)); return f;
}
#define FMA2(d,a,b) asm("fma.rn.f32x2 %0, %1, %2, %0;" : "+l"(d) : "l"(a), "l"(b))
#define MUL2(d,a,b) asm("mul.rn.f32x2 %0, %1, %2;" : "=l"(d) : "l"(a), "l"(b))

__device__ __forceinline__ float tf32r(float x) {
    float y; asm("cvt.rna.tf32.f32 %0, %1;" : "=f"(y) : "f"(x)); return y;
}

// warp-level tf32 MMA (arch-portable PTX, works on bare sm_103 target)
__device__ __forceinline__ void mma_tf32(float* d, uint32_t a0, uint32_t a1,
                                         uint32_t a2, uint32_t a3,
                                         uint32_t b0, uint32_t b1) {
    asm volatile(
        "mma.sync.aligned.m16n8k8.row.col.f32.tf32.tf32.f32 "
        "{%0,%1,%2,%3}, {%4,%5,%6,%7}, {%8,%9}, {%0,%1,%2,%3};"
        : "+f"(d[0]), "+f"(d[1]), "+f"(d[2]), "+f"(d[3])
        : "r"(a0), "r"(a1), "r"(a2), "r"(a3), "r"(b0), "r"(b1));
}

// ---------------- scratch ----------------
__device__ float g_wc[C*CM];            // comp weights [c][m], BN-scaled
__device__ float g_weB[18*112*32];      // enc weights [chunk][112 o][32 c], tf32
__device__ float g_W1T[B*4096*CM];      // conv1x1+SiLU, px-major, tf32-rounded
__device__ float g_W2[B*CO*4096];       // conv3x3+BN logits

// ---------------------------------------------------------------------------
// K0: fold BN scale; build k1 weights + padded tf32 B chunks for k2
// ---------------------------------------------------------------------------
__global__ void k0_prep(const float* __restrict__ cw, const float* __restrict__ cg,
                        const float* __restrict__ ew, const float* __restrict__ eg) {
    int i = blockIdx.x * blockDim.x + threadIdx.x;
    const float s = rsqrtf(1.0f + 1e-5f);
    if (i < C*CM) {
        int c = i >> 6, m = i & 63;
        g_wc[i] = cw[m*C + c] * (cg[m] * s);
    }
    if (i < 18*112*32) {
        int chunk = i / 3584;
        int r     = i - chunk*3584;
        int o     = r >> 5, ck = r & 31;
        int t     = chunk >> 1, ch = chunk & 1;
        float v = 0.f;
        if (o < 100) {
            int c = ch*32 + ck;
            v = tf32r(ew[(o*CM + c)*9 + t] * (eg[o] * s));
        }
        g_weB[i] = v;
    }
}

// ---------------------------------------------------------------------------
// K1: 1x1 conv (128->64) + BN bias + SiLU -> W1T [b][px][c], tf32-rounded
// ---------------------------------------------------------------------------
__global__ __launch_bounds__(256) void k1_comp(const float* __restrict__ X,
                                               const float* __restrict__ cb) {
    __shared__ float xs[16*64];
    __shared__ float ws[16*64];
    int blk = blockIdx.x;
    int b   = blk >> 6;
    int hw0 = (blk & 63) * 64;
    int tid = threadIdx.x, mg = tid >> 4, pxl = (tid & 15) * 4;

    u64 acc[4][2];
#pragma unroll
    for (int o = 0; o < 4; o++) { acc[o][0] = 0ull; acc[o][1] = 0ull; }

    for (int c0 = 0; c0 < C; c0 += 16) {
        __syncthreads();
        {
            int c = tid >> 4, px = (tid & 15) * 4;
            *(float4*)&xs[c*64 + px] =
                *(const float4*)&X[(b*C + c0 + c)*4096 + hw0 + px];
            *(float4*)&ws[tid*4] = *(const float4*)&g_wc[c0*64 + tid*4];
        }
        __syncthreads();
#pragma unroll
        for (int c = 0; c < 16; c++) {
            float4 w = *(const float4*)&ws[c*64 + mg*4];
            u64 w0 = pk(w.x,w.x), w1 = pk(w.y,w.y), w2 = pk(w.z,w.z), w3 = pk(w.w,w.w);
            u64 xa = *(const u64*)&xs[c*64 + pxl];
            u64 xb = *(const u64*)&xs[c*64 + pxl + 2];
            FMA2(acc[0][0], w0, xa); FMA2(acc[0][1], w0, xb);
            FMA2(acc[1][0], w1, xa); FMA2(acc[1][1], w1, xb);
            FMA2(acc[2][0], w2, xa); FMA2(acc[2][1], w2, xb);
            FMA2(acc[3][0], w3, xa); FMA2(acc[3][1], w3, xb);
        }
    }
    float vals[4][4];
#pragma unroll
    for (int o = 0; o < 4; o++) {
        float bias = cb[mg*4 + o];
#pragma unroll
        for (int j = 0; j < 2; j++) {
            float2 v = upk(acc[o][j]);
            float z0 = v.x + bias, z1 = v.y + bias;
            vals[o][j*2]   = tf32r(z0 / (1.0f + __expf(-z0)));
            vals[o][j*2+1] = tf32r(z1 / (1.0f + __expf(-z1)));
        }
    }
#pragma unroll
    for (int p = 0; p < 4; p++) {
        int px = hw0 + pxl + p;
        *(float4*)&g_W1T[((b*4096 + px) << 6) + mg*4] =
            make_float4(vals[0][p], vals[1][p], vals[2][p], vals[3][p]);
    }
}

// ---------------------------------------------------------------------------
// K2: 3x3 conv (64->100) + BN bias via warp-level tf32 MMA (m16n8k8).
// (unchanged — protected win from R11)
// ---------------------------------------------------------------------------
__global__ __launch_bounds__(256) void k2_enc(const float* __restrict__ eb) {
    __shared__ float As[64*36];     // [px][32k] pitch 36
    __shared__ float Bs[112*36];    // [o][32k]  pitch 36
    int blk = blockIdx.x, b = blk >> 6, y = blk & 63;
    int tid = threadIdx.x, wid = tid >> 5, lane = tid & 31;
    int mt = wid >> 1, half = wid & 1;
    int px0 = mt*16;
    int arow = lane >> 2, acol = lane & 3;

    float d[7][4];
#pragma unroll
    for (int nt = 0; nt < 7; nt++)
#pragma unroll
        for (int j = 0; j < 4; j++) d[nt][j] = 0.f;

    int spx = tid >> 2, sq = tid & 3;          // A staging coords

    for (int t = 0; t < 9; t++) {
        int ti = t/3 - 1, tj = t%3 - 1;
        int yy = y + ti;
        int xx = spx + tj;
        bool valid = ((unsigned)yy < 64u) && ((unsigned)xx < 64u);
        const float4* asrc = (const float4*)
            &g_W1T[((b*4096 + yy*64 + xx) << 6) + sq*8];
        for (int ch = 0; ch < 2; ch++) {
            __syncthreads();
            {   // stage A: 64 px x 32 c
                float4 v0, v1;
                if (valid) { v0 = asrc[ch*8]; v1 = asrc[ch*8 + 1]; }
                else { v0 = make_float4(0,0,0,0); v1 = v0; }
                float* dst = &As[spx*36 + sq*8];
                *(float2*)(dst)     = make_float2(v0.x, v0.y);
                *(float2*)(dst + 2) = make_float2(v0.z, v0.w);
                *(float2*)(dst + 4) = make_float2(v1.x, v1.y);
                *(float2*)(dst + 6) = make_float2(v1.z, v1.w);
            }
            {   // stage B: 112 o x 32 c (896 float4)
                const float4* src = (const float4*)&g_weB[(t*2 + ch)*3584];
                for (int idx = tid; idx < 896; idx += 256) {
                    float4 v = src[idx];
                    int o = idx >> 3, q = idx & 7;
                    float* dst = &Bs[o*36 + q*4];
                    *(float2*)(dst)     = make_float2(v.x, v.y);
                    *(float2*)(dst + 2) = make_float2(v.z, v.w);
                }
            }
            __syncthreads();
#pragma unroll
            for (int kt = 0; kt < 4; kt++) {
                const float* ab = &As[(px0 + arow)*36 + kt*8 + acol];
                uint32_t a0 = __float_as_uint(ab[0]);
                uint32_t a1 = __float_as_uint(ab[8*36]);
                uint32_t a2 = __float_as_uint(ab[4]);
                uint32_t a3 = __float_as_uint(ab[8*36 + 4]);
#pragma unroll
                for (int nt = 0; nt < 7; nt++) {
                    const float* bb = &Bs[(half*56 + nt*8 + arow)*36 + kt*8 + acol];
                    uint32_t b0 = __float_as_uint(bb[0]);
                    uint32_t b1 = __float_as_uint(bb[4]);
                    mma_tf32(d[nt], a0, a1, a2, a3, b0, b1);
                }
            }
        }
    }

    // epilogue: d0:(pxA,o) d1:(pxA,o+1) d2:(pxB,o) d3:(pxB,o+1)
    int pxA = y*64 + px0 + arow;
    int pxB = pxA + 8;
#pragma unroll
    for (int nt = 0; nt < 7; nt++) {
        int o = half*56 + nt*8 + acol*2;
        if (o < 100) {
            float bias = eb[o];
            float* base = &g_W2[(b*CO + o)*4096];
            base[pxA] = d[nt][0] + bias;
            base[pxB] = d[nt][2] + bias;
        }
        if (o + 1 < 100) {
            float bias = eb[o + 1];
            float* base = &g_W2[(b*CO + o + 1)*4096];
            base[pxA] = d[nt][1] + bias;
            base[pxB] = d[nt][3] + bias;
        }
    }
}

// ---------------------------------------------------------------------------
// K3: pixel-shuffle + softmax(25) + CARAFE combine.
// Same proven body, but w23 lives in SMEM instead of registers:
// regs ~128 -> ~78, so 6 blocks/SM (24 warps) instead of 4 (16 warps).
// Inner body per (channel, tap): LDS.32(x) + pk + LDS.64(w23) + 2 FFMA2.
// w23s layout [k][tid] -> LDS.64 conflict-free.
// ---------------------------------------------------------------------------
__global__ __launch_bounds__(128, 6) void k3_carafe(const float* __restrict__ X,
                                                    float* __restrict__ out) {
    __shared__ float xs[4*240];       // [c][12 rows][pitch 20]
    __shared__ u64  w23s[25*128];     // [k][tid]
    int blk    = blockIdx.x;
    int cq     = blk >> 7;
    int tileid = blk & 127;
    int b  = tileid >> 5;
    int t  = tileid & 31;
    int ty = t >> 2, tx = t & 3;
    int tid = threadIdx.x;
    int py  = tid >> 4, pxl = tid & 15;
    int y0g = ty*8 + py, x0g = tx*16 + pxl;

    u64 w01[25];
    {
        const float* base = g_W2 + (size_t)b*CO*4096 + y0g*64 + x0g;
        float s0 = 0.f, s1 = 0.f, s2 = 0.f, s3 = 0.f;
        u64 w23r[25];
#pragma unroll
        for (int k = 0; k < 25; k++) {
            float e0 = __expf(base[(k*4 + 0)*4096]); s0 += e0;
            float e1 = __expf(base[(k*4 + 1)*4096]); s1 += e1;
            w01[k] = pk(e0, e1);
            float e2 = __expf(base[(k*4 + 2)*4096]); s2 += e2;
            float e3 = __expf(base[(k*4 + 3)*4096]); s3 += e3;
            w23r[k] = pk(e2, e3);
        }
        u64 i01 = pk(1.0f/s0, 1.0f/s1);
        u64 i23 = pk(1.0f/s2, 1.0f/s3);
#pragma unroll
        for (int k = 0; k < 25; k++) {
            MUL2(w01[k], w01[k], i01);
            MUL2(w23r[k], w23r[k], i23);
            w23s[k*128 + tid] = w23r[k];
        }
    }

    int cbase = cq*32;
    int ybase = ty*8 - 2, xbase = tx*16 - 2;
    for (int c0 = 0; c0 < 32; c0 += 4) {
        __syncthreads();
        for (int k = tid; k < 960; k += 128) {
            int c = k / 240, p = k - c*240, r = p / 20, cl = p - r*20;
            int y = ybase + r, x = xbase + cl;
            float v = 0.f;
            if ((unsigned)y < 64u && (unsigned)x < 64u)
                v = X[((b*C + cbase + c0 + c)*64 + y)*64 + x];
            xs[c*240 + r*20 + cl] = v;
        }
        __syncthreads();
#pragma unroll
        for (int c = 0; c < 4; c++) {
            u64 a01 = 0ull, a23 = 0ull;
            const float* xp = &xs[c*240 + py*20 + pxl];
#pragma unroll
            for (int i = 0; i < 5; i++)
#pragma unroll
                for (int j = 0; j < 5; j++) {
                    float xv = xp[i*20 + j];
                    u64 xx = pk(xv, xv);
                    int kk = i*5 + j;
                    FMA2(a01, w01[kk], xx);
                    FMA2(a23, w23s[kk*128 + tid], xx);
                }
            int ch = cbase + c0 + c;
            size_t ob = ((size_t)(b*C + ch)*HO + 2*y0g)*WO + 2*x0g;
            float2 top = upk(a01), bot = upk(a23);
            *(float2*)&out[ob]      = top;
            *(float2*)&out[ob + WO] = bot;
        }
    }
}

// ---------------------------------------------------------------------------
extern "C" void kernel_launch(void* const* d_in, const int* in_sizes, int n_in,
                              void* d_out, int out_size) {
    const float* X      = (const float*)d_in[0];
    const float* comp_w = (const float*)d_in[1];
    const float* comp_g = (const float*)d_in[2];
    const float* comp_b = (const float*)d_in[3];
    const float* enc_w  = (const float*)d_in[4];
    const float* enc_g  = (const float*)d_in[5];
    const float* enc_b  = (const float*)d_in[6];
    float* out = (float*)d_out;

    k0_prep  <<<252, 256>>>(comp_w, comp_g, enc_w, enc_g);
    k1_comp  <<<256, 256>>>(X, comp_b);
    k2_enc   <<<256, 256>>>(enc_b);
    k3_carafe<<<512, 128>>>(X, out);
}

// round 17
// speedup vs baseline: 1.4701x; 1.4701x over previous
#include <cuda_runtime.h>
#include <cuda_bf16.h>
#include <cstdint>

#define B 4
#define C 128
#define CM 64
#define CO 100
#define HO 128
#define WO 128

typedef unsigned long long u64;

// ---------------- packed f32x2 helpers (k1/k3 scalar paths) ----------------
__device__ __forceinline__ u64 pk(float lo, float hi) {
    u64 r; asm("mov.b64 %0, {%1,%2};" : "=l"(r) : "f"(lo), "f"(hi)); return r;
}
__device__ __forceinline__ float2 upk(u64 v) {
    float2 f; asm("mov.b64 {%0,%1}, %2;" : "=f"(f.x), "=f"(f.y) : "l"(v)); return f;
}
#define FMA2(d,a,b) asm("fma.rn.f32x2 %0, %1, %2, %0;" : "+l"(d) : "l"(a), "l"(b))
#define MUL2(d,a,b) asm("mul.rn.f32x2 %0, %1, %2;" : "=l"(d) : "l"(a), "l"(b))

__device__ __forceinline__ float tf32r(float x) {
    float y; asm("cvt.rna.tf32.f32 %0, %1;" : "=f"(y) : "f"(x)); return y;
}

// warp-level tf32 MMA (arch-portable PTX, works on bare sm_103 target)
__device__ __forceinline__ void mma_tf32(float* d, uint32_t a0, uint32_t a1,
                                         uint32_t a2, uint32_t a3,
                                         uint32_t b0, uint32_t b1) {
    asm volatile(
        "mma.sync.aligned.m16n8k8.row.col.f32.tf32.tf32.f32 "
        "{%0,%1,%2,%3}, {%4,%5,%6,%7}, {%8,%9}, {%0,%1,%2,%3};"
        : "+f"(d[0]), "+f"(d[1]), "+f"(d[2]), "+f"(d[3])
        : "r"(a0), "r"(a1), "r"(a2), "r"(a3), "r"(b0), "r"(b1));
}

// ---------------- scratch ----------------
__device__ float g_wc[C*CM];            // comp weights [c][m], BN-scaled
__device__ float g_weB[18*112*32];      // enc weights [chunk][112 o][32 c], tf32
__device__ float g_W1T[B*4096*CM];      // conv1x1+SiLU, px-major, tf32-rounded
__device__ float g_W2[B*CO*4096];       // conv3x3+BN logits

// ---------------------------------------------------------------------------
// K0: fold BN scale; build k1 weights + padded tf32 B chunks for k2
// ---------------------------------------------------------------------------
__global__ void k0_prep(const float* __restrict__ cw, const float* __restrict__ cg,
                        const float* __restrict__ ew, const float* __restrict__ eg) {
    int i = blockIdx.x * blockDim.x + threadIdx.x;
    const float s = rsqrtf(1.0f + 1e-5f);
    if (i < C*CM) {
        int c = i >> 6, m = i & 63;
        g_wc[i] = cw[m*C + c] * (cg[m] * s);
    }
    if (i < 18*112*32) {
        int chunk = i / 3584;
        int r     = i - chunk*3584;
        int o     = r >> 5, ck = r & 31;
        int t     = chunk >> 1, ch = chunk & 1;
        float v = 0.f;
        if (o < 100) {
            int c = ch*32 + ck;
            v = tf32r(ew[(o*CM + c)*9 + t] * (eg[o] * s));
        }
        g_weB[i] = v;
    }
}

// ---------------------------------------------------------------------------
// K1: 1x1 conv (128->64) + BN bias + SiLU -> W1T [b][px][c], tf32-rounded
// ---------------------------------------------------------------------------
__global__ __launch_bounds__(256) void k1_comp(const float* __restrict__ X,
                                               const float* __restrict__ cb) {
    __shared__ float xs[16*64];
    __shared__ float ws[16*64];
    int blk = blockIdx.x;
    int b   = blk >> 6;
    int hw0 = (blk & 63) * 64;
    int tid = threadIdx.x, mg = tid >> 4, pxl = (tid & 15) * 4;

    u64 acc[4][2];
#pragma unroll
    for (int o = 0; o < 4; o++) { acc[o][0] = 0ull; acc[o][1] = 0ull; }

    for (int c0 = 0; c0 < C; c0 += 16) {
        __syncthreads();
        {
            int c = tid >> 4, px = (tid & 15) * 4;
            *(float4*)&xs[c*64 + px] =
                *(const float4*)&X[(b*C + c0 + c)*4096 + hw0 + px];
            *(float4*)&ws[tid*4] = *(const float4*)&g_wc[c0*64 + tid*4];
        }
        __syncthreads();
#pragma unroll
        for (int c = 0; c < 16; c++) {
            float4 w = *(const float4*)&ws[c*64 + mg*4];
            u64 w0 = pk(w.x,w.x), w1 = pk(w.y,w.y), w2 = pk(w.z,w.z), w3 = pk(w.w,w.w);
            u64 xa = *(const u64*)&xs[c*64 + pxl];
            u64 xb = *(const u64*)&xs[c*64 + pxl + 2];
            FMA2(acc[0][0], w0, xa); FMA2(acc[0][1], w0, xb);
            FMA2(acc[1][0], w1, xa); FMA2(acc[1][1], w1, xb);
            FMA2(acc[2][0], w2, xa); FMA2(acc[2][1], w2, xb);
            FMA2(acc[3][0], w3, xa); FMA2(acc[3][1], w3, xb);
        }
    }
    float vals[4][4];
#pragma unroll
    for (int o = 0; o < 4; o++) {
        float bias = cb[mg*4 + o];
#pragma unroll
        for (int j = 0; j < 2; j++) {
            float2 v = upk(acc[o][j]);
            float z0 = v.x + bias, z1 = v.y + bias;
            vals[o][j*2]   = tf32r(z0 / (1.0f + __expf(-z0)));
            vals[o][j*2+1] = tf32r(z1 / (1.0f + __expf(-z1)));
        }
    }
#pragma unroll
    for (int p = 0; p < 4; p++) {
        int px = hw0 + pxl + p;
        *(float4*)&g_W1T[((b*4096 + px) << 6) + mg*4] =
            make_float4(vals[0][p], vals[1][p], vals[2][p], vals[3][p]);
    }
}

// ---------------------------------------------------------------------------
// K2: 3x3 conv (64->100) + BN bias via warp-level tf32 MMA (m16n8k8).
// (unchanged — protected win from R11)
// ---------------------------------------------------------------------------
__global__ __launch_bounds__(256) void k2_enc(const float* __restrict__ eb) {
    __shared__ float As[64*36];     // [px][32k] pitch 36
    __shared__ float Bs[112*36];    // [o][32k]  pitch 36
    int blk = blockIdx.x, b = blk >> 6, y = blk & 63;
    int tid = threadIdx.x, wid = tid >> 5, lane = tid & 31;
    int mt = wid >> 1, half = wid & 1;
    int px0 = mt*16;
    int arow = lane >> 2, acol = lane & 3;

    float d[7][4];
#pragma unroll
    for (int nt = 0; nt < 7; nt++)
#pragma unroll
        for (int j = 0; j < 4; j++) d[nt][j] = 0.f;

    int spx = tid >> 2, sq = tid & 3;          // A staging coords

    for (int t = 0; t < 9; t++) {
        int ti = t/3 - 1, tj = t%3 - 1;
        int yy = y + ti;
        int xx = spx + tj;
        bool valid = ((unsigned)yy < 64u) && ((unsigned)xx < 64u);
        const float4* asrc = (const float4*)
            &g_W1T[((b*4096 + yy*64 + xx) << 6) + sq*8];
        for (int ch = 0; ch < 2; ch++) {
            __syncthreads();
            {   // stage A: 64 px x 32 c
                float4 v0, v1;
                if (valid) { v0 = asrc[ch*8]; v1 = asrc[ch*8 + 1]; }
                else { v0 = make_float4(0,0,0,0); v1 = v0; }
                float* dst = &As[spx*36 + sq*8];
                *(float2*)(dst)     = make_float2(v0.x, v0.y);
                *(float2*)(dst + 2) = make_float2(v0.z, v0.w);
                *(float2*)(dst + 4) = make_float2(v1.x, v1.y);
                *(float2*)(dst + 6) = make_float2(v1.z, v1.w);
            }
            {   // stage B: 112 o x 32 c (896 float4)
                const float4* src = (const float4*)&g_weB[(t*2 + ch)*3584];
                for (int idx = tid; idx < 896; idx += 256) {
                    float4 v = src[idx];
                    int o = idx >> 3, q = idx & 7;
                    float* dst = &Bs[o*36 + q*4];
                    *(float2*)(dst)     = make_float2(v.x, v.y);
                    *(float2*)(dst + 2) = make_float2(v.z, v.w);
                }
            }
            __syncthreads();
#pragma unroll
            for (int kt = 0; kt < 4; kt++) {
                const float* ab = &As[(px0 + arow)*36 + kt*8 + acol];
                uint32_t a0 = __float_as_uint(ab[0]);
                uint32_t a1 = __float_as_uint(ab[8*36]);
                uint32_t a2 = __float_as_uint(ab[4]);
                uint32_t a3 = __float_as_uint(ab[8*36 + 4]);
#pragma unroll
                for (int nt = 0; nt < 7; nt++) {
                    const float* bb = &Bs[(half*56 + nt*8 + arow)*36 + kt*8 + acol];
                    uint32_t b0 = __float_as_uint(bb[0]);
                    uint32_t b1 = __float_as_uint(bb[4]);
                    mma_tf32(d[nt], a0, a1, a2, a3, b0, b1);
                }
            }
        }
    }

    // epilogue
    int pxA = y*64 + px0 + arow;
    int pxB = pxA + 8;
#pragma unroll
    for (int nt = 0; nt < 7; nt++) {
        int o = half*56 + nt*8 + acol*2;
        if (o < 100) {
            float bias = eb[o];
            float* base = &g_W2[(b*CO + o)*4096];
            base[pxA] = d[nt][0] + bias;
            base[pxB] = d[nt][2] + bias;
        }
        if (o + 1 < 100) {
            float bias = eb[o + 1];
            float* base = &g_W2[(b*CO + o + 1)*4096];
            base[pxA] = d[nt][1] + bias;
            base[pxB] = d[nt][3] + bias;
        }
    }
}

// ---------------------------------------------------------------------------
// K3: pixel-shuffle + softmax(25) + CARAFE combine.
// Weights (all 4 subpix) in registers as in the proven 30.6us version.
// NEW: X staged DUPLICATED (v,v) in smem -> per tap 1 LDS.64 + 2 FFMA2,
// zero MOVs; channels processed in PAIRS -> 4 independent FFMA2 chains.
// Per channel: 75 issues (was ~125) for the same 200 lane-FMA.
// ---------------------------------------------------------------------------
__global__ __launch_bounds__(128, 4) void k3_carafe(const float* __restrict__ X,
                                                    float* __restrict__ out) {
    __shared__ __align__(16) u64 xsd[4*240];   // [4 ch][12 rows][pitch 20] dup
    int blk    = blockIdx.x;
    int cq     = blk >> 7;
    int tileid = blk & 127;
    int b  = tileid >> 5;
    int t  = tileid & 31;
    int ty = t >> 2, tx = t & 3;
    int tid = threadIdx.x;
    int py  = tid >> 4, pxl = tid & 15;
    int y0g = ty*8 + py, x0g = tx*16 + pxl;

    u64 w01[25], w23[25];
    {
        const float* base = g_W2 + (size_t)b*CO*4096 + y0g*64 + x0g;
        float s0 = 0.f, s1 = 0.f, s2 = 0.f, s3 = 0.f;
#pragma unroll
        for (int k = 0; k < 25; k++) {
            float e0 = __expf(base[(k*4 + 0)*4096]); s0 += e0;
            float e1 = __expf(base[(k*4 + 1)*4096]); s1 += e1;
            w01[k] = pk(e0, e1);
            float e2 = __expf(base[(k*4 + 2)*4096]); s2 += e2;
            float e3 = __expf(base[(k*4 + 3)*4096]); s3 += e3;
            w23[k] = pk(e2, e3);
        }
        u64 i01 = pk(1.0f/s0, 1.0f/s1);
        u64 i23 = pk(1.0f/s2, 1.0f/s3);
#pragma unroll
        for (int k = 0; k < 25; k++) {
            MUL2(w01[k], w01[k], i01);
            MUL2(w23[k], w23[k], i23);
        }
    }

    int cbase = cq*32;
    int ybase = ty*8 - 2, xbase = tx*16 - 2;
    for (int c0 = 0; c0 < 32; c0 += 4) {
        __syncthreads();
        for (int k = tid; k < 960; k += 128) {
            int c = k / 240, p = k - c*240, r = p / 20, cl = p - r*20;
            int y = ybase + r, x = xbase + cl;
            float v = 0.f;
            if ((unsigned)y < 64u && (unsigned)x < 64u)
                v = X[((b*C + cbase + c0 + c)*64 + y)*64 + x];
            *(float2*)&xsd[k] = make_float2(v, v);
        }
        __syncthreads();
#pragma unroll
        for (int cp = 0; cp < 2; cp++) {       // channel pairs
            u64 aA01 = 0ull, aA23 = 0ull, aB01 = 0ull, aB23 = 0ull;
            const u64* xp = &xsd[cp*480 + py*20 + pxl];
#pragma unroll
            for (int i = 0; i < 5; i++)
#pragma unroll
                for (int j = 0; j < 5; j++) {
                    int off = i*20 + j;
                    u64 xa = xp[off];
                    u64 xb = xp[off + 240];
                    int kk = i*5 + j;
                    FMA2(aA01, w01[kk], xa);
                    FMA2(aA23, w23[kk], xa);
                    FMA2(aB01, w01[kk], xb);
                    FMA2(aB23, w23[kk], xb);
                }
            int ch = cbase + c0 + cp*2;
            size_t ob = ((size_t)(b*C + ch)*HO + 2*y0g)*WO + 2*x0g;
            *(float2*)&out[ob]      = upk(aA01);
            *(float2*)&out[ob + WO] = upk(aA23);
            ob += (size_t)HO*WO;
            *(float2*)&out[ob]      = upk(aB01);
            *(float2*)&out[ob + WO] = upk(aB23);
        }
    }
}

// ---------------------------------------------------------------------------
extern "C" void kernel_launch(void* const* d_in, const int* in_sizes, int n_in,
                              void* d_out, int out_size) {
    const float* X      = (const float*)d_in[0];
    const float* comp_w = (const float*)d_in[1];
    const float* comp_g = (const float*)d_in[2];
    const float* comp_b = (const float*)d_in[3];
    const float* enc_w  = (const float*)d_in[4];
    const float* enc_g  = (const float*)d_in[5];
    const float* enc_b  = (const float*)d_in[6];
    float* out = (float*)d_out;

    k0_prep  <<<252, 256>>>(comp_w, comp_g, enc_w, enc_g);
    k1_comp  <<<256, 256>>>(X, comp_b);
    k2_enc   <<<256, 256>>>(enc_b);
    k3_carafe<<<512, 128>>>(X, out);
}